// round 10
// baseline (speedup 1.0000x reference)
#include <cuda_runtime.h>
#include <cstddef>

#define BATCH   8
#define NPTS    8192
#define CFEAT   32
#define NPOINT  1024
#define NSAMPLE 32
#define OUTC    35            // 3 (centered xyz) + 32 (features)
#define R2      0.0625f       // 0.25^2, exact in fp32

typedef unsigned long long u64;

// ---------------------------------------------------------------------------
__device__ __forceinline__ unsigned redux_max_u32(unsigned v) {
    unsigned r;
    asm volatile("redux.sync.max.u32 %0, %1, 0xffffffff;" : "=r"(r) : "r"(v));
    return r;
}
__device__ __forceinline__ int redux_min_s32(int v) {
    int r;
    asm volatile("redux.sync.min.s32 %0, %1, 0xffffffff;" : "=r"(r) : "r"(v));
    return r;
}

// Packed f32x2 helpers (Blackwell). Each half rounds with .rn — bit-identical
// to the scalar op on that half, so FPS distance math stays bit-exact.
__device__ __forceinline__ u64 pk2(float lo, float hi) {
    u64 r; asm("mov.b64 %0, {%1, %2};" : "=l"(r) : "f"(lo), "f"(hi)); return r;
}
__device__ __forceinline__ float2 upk2(u64 v) {
    float lo, hi; asm("mov.b64 {%0, %1}, %2;" : "=f"(lo), "=f"(hi) : "l"(v));
    return make_float2(lo, hi);
}
__device__ __forceinline__ u64 addx2(u64 a, u64 b) {
    u64 r; asm("add.rn.f32x2 %0, %1, %2;" : "=l"(r) : "l"(a), "l"(b)); return r;
}
__device__ __forceinline__ u64 mulx2(u64 a, u64 b) {
    u64 r; asm("mul.rn.f32x2 %0, %1, %2;" : "=l"(r) : "l"(a), "l"(b)); return r;
}

// ---------------------------------------------------------------------------
// Kernel 1: FPS — round-2 structure (best measured: all warps update every
// iteration, two-level reduction), with ONE change: the next center's coords
// are published through shared memory by the warp-argmax owner lane instead
// of being re-fetched from global memory (cold L2, ~240cyc on the serial
// chain). No pruning, no partition — both measured as net losses (r3-r9).
//
// Numerics (bit-exact vs XLA reference, proven rel_err = 0.0):
//   d2 = ((dx*dx + dy*dy) + dz*dz) via .rn packed ops (no FMA contraction),
//   dx = px + (-lx) (exact negation == subtraction),
//   dist = fminf(dist, d2) (exact),
//   argmax = first occurrence: ascending-j strict '>' within a lane,
//   min original index across lanes/warps on ties.
// ---------------------------------------------------------------------------
__global__ __launch_bounds__(1024, 1)
void fps_kernel(const float* __restrict__ xyz, float* __restrict__ new_xyz) {
    const int b = blockIdx.x;
    const int t = threadIdx.x;
    const int w = t >> 5;
    const float* X = xyz + (size_t)b * NPTS * 3;
    float* O = new_xyz + (size_t)b * NPOINT * 3;

    // Pair q holds points i0 = (2q)*1024 + t (lo) and i1 = (2q+1)*1024 + t
    // (hi), so dist[j] corresponds to original index j*1024 + t.
    u64 pxp[4], pyp[4], pzp[4];
    float dist[8];
#pragma unroll
    for (int q = 0; q < 4; q++) {
        const int i0 = (2 * q) * 1024 + t;
        const int i1 = (2 * q + 1) * 1024 + t;
        pxp[q] = pk2(X[3 * i0 + 0], X[3 * i1 + 0]);
        pyp[q] = pk2(X[3 * i0 + 1], X[3 * i1 + 1]);
        pzp[q] = pk2(X[3 * i0 + 2], X[3 * i1 + 2]);
        dist[2 * q] = 1e38f;
        dist[2 * q + 1] = 1e38f;
    }

    __shared__ uint2  s_kv[32];        // per-warp (dist bits, orig idx)
    __shared__ float4 s_cd[32];        // per-warp candidate coords
    __shared__ float  s_ctr[4];        // winner coords broadcast

    float lx = X[0], ly = X[1], lz = X[2];   // first center = point 0
    if (t == 0) { O[0] = lx; O[1] = ly; O[2] = lz; }

    for (int k = 1; k < NPOINT; k++) {
        // ---- update + per-lane argmax ----
        const unsigned nbx = __float_as_uint(lx) ^ 0x80000000u;
        const unsigned nby = __float_as_uint(ly) ^ 0x80000000u;
        const unsigned nbz = __float_as_uint(lz) ^ 0x80000000u;
        const u64 nlx2 = pk2(__uint_as_float(nbx), __uint_as_float(nbx));
        const u64 nly2 = pk2(__uint_as_float(nby), __uint_as_float(nby));
        const u64 nlz2 = pk2(__uint_as_float(nbz), __uint_as_float(nbz));

#pragma unroll
        for (int q = 0; q < 4; q++) {
            const u64 dx = addx2(pxp[q], nlx2);
            const u64 dy = addx2(pyp[q], nly2);
            const u64 dz = addx2(pzp[q], nlz2);
            // ((dx^2 + dy^2) + dz^2) — same association as the reference.
            const u64 s = addx2(addx2(mulx2(dx, dx), mulx2(dy, dy)),
                                mulx2(dz, dz));
            const float2 d2 = upk2(s);
            dist[2 * q]     = fminf(dist[2 * q],     d2.x);
            dist[2 * q + 1] = fminf(dist[2 * q + 1], d2.y);
        }

        // Per-lane argmax, first occurrence (ascending j == ascending index).
        float best = -1.0f;   // dists >= 0: first compare always wins
        int bi = 0, jb = 0;
#pragma unroll
        for (int j = 0; j < 8; j++) {
            const float nd = dist[j];
            if (nd > best) { best = nd; bi = j * 1024 + t; jb = j; }
        }

        // ---- warp reduce: max key, then min original index on ties ----
        const unsigned vb = __float_as_uint(best);
        const unsigned wmax = redux_max_u32(vb);
        const int cand = (vb == wmax) ? bi : 0x7fffffff;
        const int wimin = redux_min_s32(cand);

        // Owner lane (unique: indices are distinct) publishes key+idx+coords.
        if (cand == wimin) {
            float cxv = 0.f, cyv = 0.f, czv = 0.f;
#pragma unroll
            for (int j = 0; j < 8; j++) {
                if (j == jb) {
                    const float2 xx = upk2(pxp[j >> 1]);
                    const float2 yy = upk2(pyp[j >> 1]);
                    const float2 zz = upk2(pzp[j >> 1]);
                    cxv = (j & 1) ? xx.y : xx.x;
                    cyv = (j & 1) ? yy.y : yy.x;
                    czv = (j & 1) ? zz.y : zz.x;
                }
            }
            s_kv[w] = make_uint2(wmax, (unsigned)wimin);
            s_cd[w] = make_float4(cxv, cyv, czv, 0.f);
        }
        __syncthreads();

        // ---- second level (warp 0): pick winner slot, broadcast coords ----
        if (t < 32) {
            const uint2 kv = s_kv[t];
            const unsigned m2 = redux_max_u32(kv.x);
            const int wi = redux_min_s32((kv.x == m2) ? (int)kv.y : 0x7fffffff);
            // Exactly one slot matches (indices unique across warps).
            if (kv.x == m2 && (int)kv.y == wi) {
                const float4 cd = s_cd[t];
                s_ctr[0] = cd.x; s_ctr[1] = cd.y; s_ctr[2] = cd.z;
                O[3 * k] = cd.x; O[3 * k + 1] = cd.y; O[3 * k + 2] = cd.z;
            }
        }
        __syncthreads();

        lx = s_ctr[0]; ly = s_ctr[1]; lz = s_ctr[2];   // LDS broadcast
    }
}

// ---------------------------------------------------------------------------
// Kernel 2: fused ball query + grouping. One warp per center. The in-radius
// scan batches 8 ballots (256 points) per early-exit check: loads/math are
// independent (deep MLP); the serialized cnt/ballot chain is 8x shorter.
// ---------------------------------------------------------------------------
__global__ __launch_bounds__(256)
void ballgroup_kernel(const float* __restrict__ xyz,
                      const float* __restrict__ points,
                      const float* __restrict__ new_xyz,
                      float* __restrict__ new_points) {
    const int gwarp = (blockIdx.x * blockDim.x + threadIdx.x) >> 5;
    const int lane  = threadIdx.x & 31;
    const int wslot = threadIdx.x >> 5;
    if (gwarp >= BATCH * NPOINT) return;

    const int b = gwarp / NPOINT;
    const int p = gwarp % NPOINT;

    const float* X   = xyz    + (size_t)b * NPTS * 3;
    const float* P   = points + (size_t)b * NPTS * CFEAT;
    const float* ctr = new_xyz + (size_t)(b * NPOINT + p) * 3;
    const float cx = ctr[0], cy = ctr[1], cz = ctr[2];

    __shared__ int sidx[8][NSAMPLE];

    const unsigned lmask = (1u << lane) - 1u;
    int cnt = 0;
    for (int sb = 0; sb < NPTS && cnt < NSAMPLE; sb += 256) {
        unsigned m[8];
#pragma unroll
        for (int c = 0; c < 8; c++) {
            const int i = sb + c * 32 + lane;
            const float dx = X[3 * i + 0] - cx;
            const float dy = X[3 * i + 1] - cy;
            const float dz = X[3 * i + 2] - cz;
            const float d2 = __fadd_rn(__fadd_rn(__fmul_rn(dx, dx),
                                                 __fmul_rn(dy, dy)),
                                       __fmul_rn(dz, dz));
            m[c] = __ballot_sync(0xffffffff, d2 < R2);
        }
#pragma unroll
        for (int c = 0; c < 8; c++) {
            const int i = sb + c * 32 + lane;
            const bool in = (m[c] >> lane) & 1u;
            const int pos = cnt + __popc(m[c] & lmask);
            if (in && pos < NSAMPLE) sidx[wslot][pos] = i;
            cnt += __popc(m[c]);
        }
    }
    __syncwarp();

    // Pad: every center contains itself (d2 == 0 < R2), so cnt >= 1.
    const int nvalid = cnt < NSAMPLE ? cnt : NSAMPLE;
    const int first  = sidx[wslot][0];
    const int myidx  = (lane < nvalid) ? sidx[wslot][lane] : first;
    sidx[wslot][lane] = myidx;
    __syncwarp();

    float* OUT = new_points + (size_t)(b * NPOINT + p) * NSAMPLE * OUTC;
    const float cc = (lane == 0) ? cx : ((lane == 1) ? cy : cz);

#pragma unroll
    for (int s0 = 0; s0 < NSAMPLE; s0 += 4) {
        int id[4];
#pragma unroll
        for (int u = 0; u < 4; u++) id[u] = sidx[wslot][s0 + u];
#pragma unroll
        for (int u = 0; u < 4; u++) {
            const int idx = id[u];
            float v;
            if (lane < 3) {
                v = X[3 * idx + lane] - cc;                   // centered xyz
            } else {
                v = P[(size_t)idx * CFEAT + (lane - 3)];      // feature 0..28
            }
            OUT[(s0 + u) * OUTC + lane] = v;
            if (lane < 3) {                                    // feature 29..31
                OUT[(s0 + u) * OUTC + 32 + lane] =
                    P[(size_t)idx * CFEAT + 29 + lane];
            }
        }
    }
}

// ---------------------------------------------------------------------------
// Launch: d_in[0] = xyz (8*8192*3 f32), d_in[1] = points (8*8192*32 f32).
// d_out = [ new_xyz : 8*1024*3 ][ new_points : 8*1024*32*35 ] f32.
// ---------------------------------------------------------------------------
extern "C" void kernel_launch(void* const* d_in, const int* in_sizes, int n_in,
                              void* d_out, int out_size) {
    const float* xyz    = (const float*)d_in[0];
    const float* points = (const float*)d_in[1];
    float* new_xyz    = (float*)d_out;
    float* new_points = new_xyz + (size_t)BATCH * NPOINT * 3;

    fps_kernel<<<BATCH, 1024>>>(xyz, new_xyz);

    const int nwarps  = BATCH * NPOINT;            // 8192 centers
    const int threads = 256;                       // 8 warps/block
    const int blocks  = (nwarps * 32) / threads;   // 1024 blocks
    ballgroup_kernel<<<blocks, threads>>>(xyz, points, new_xyz, new_points);
}

// round 11
// speedup vs baseline: 1.3845x; 1.3845x over previous
#include <cuda_runtime.h>
#include <cstddef>

#define BATCH   8
#define NPTS    8192
#define CFEAT   32
#define NPOINT  1024
#define NSAMPLE 32
#define OUTC    35            // 3 (centered xyz) + 32 (features)
#define R2      0.0625f       // 0.25^2, exact in fp32

typedef unsigned long long u64;

// ---------------------------------------------------------------------------
// Warp redux helpers (sm_80+). Called convergently by full warps only.
// ---------------------------------------------------------------------------
__device__ __forceinline__ unsigned redux_max_u32(unsigned v) {
    unsigned r;
    asm volatile("redux.sync.max.u32 %0, %1, 0xffffffff;" : "=r"(r) : "r"(v));
    return r;
}
__device__ __forceinline__ int redux_min_s32(int v) {
    int r;
    asm volatile("redux.sync.min.s32 %0, %1, 0xffffffff;" : "=r"(r) : "r"(v));
    return r;
}

// ---------------------------------------------------------------------------
// Packed f32x2 helpers (Blackwell sm_100+). Each half is rounded with .rn —
// bit-identical to the scalar op on that half, so the FPS distance math stays
// bit-exact vs the reference.
// ---------------------------------------------------------------------------
__device__ __forceinline__ u64 pk2(float lo, float hi) {
    u64 r; asm("mov.b64 %0, {%1, %2};" : "=l"(r) : "f"(lo), "f"(hi)); return r;
}
__device__ __forceinline__ float2 upk2(u64 v) {
    float lo, hi; asm("mov.b64 {%0, %1}, %2;" : "=f"(lo), "=f"(hi) : "l"(v));
    return make_float2(lo, hi);
}
__device__ __forceinline__ u64 addx2(u64 a, u64 b) {
    u64 r; asm("add.rn.f32x2 %0, %1, %2;" : "=l"(r) : "l"(a), "l"(b)); return r;
}
__device__ __forceinline__ u64 mulx2(u64 a, u64 b) {
    u64 r; asm("mul.rn.f32x2 %0, %1, %2;" : "=l"(r) : "l"(a), "l"(b)); return r;
}

// ---------------------------------------------------------------------------
// Kernel 1: furthest point sampling — round-2 version VERBATIM (best measured
// FPS: 575us). One block per batch, 1024 threads, 8 points per thread packed
// as 4 f32x2 pairs per coordinate. 1023 sequential iterations of (distance
// update fused with per-lane argmax, two-level block argmax). Center fetch
// via __ldg is an L1 hit (X is L1-resident after the init stream).
// Distance math: ((dx*dx + dy*dy) + dz*dz) with .rn ops, no FMA contraction
// — bit-matches the XLA reference (rel_err = 0.0 measured).
// dx computed as px + (-lx): exact negation, IEEE-identical to subtraction.
// ---------------------------------------------------------------------------
__global__ __launch_bounds__(1024, 1)
void fps_kernel(const float* __restrict__ xyz, float* __restrict__ new_xyz) {
    const int b = blockIdx.x;
    const float* X = xyz + (size_t)b * NPTS * 3;
    float* O = new_xyz + (size_t)b * NPOINT * 3;
    const int t = threadIdx.x;

    // Pair q holds points i0 = (2q)*1024 + t (lo) and i1 = (2q+1)*1024 + t (hi).
    u64 pxp[4], pyp[4], pzp[4];
    float dist[8];
#pragma unroll
    for (int q = 0; q < 4; q++) {
        const int i0 = (2 * q) * 1024 + t;
        const int i1 = (2 * q + 1) * 1024 + t;
        pxp[q] = pk2(X[3 * i0 + 0], X[3 * i1 + 0]);
        pyp[q] = pk2(X[3 * i0 + 1], X[3 * i1 + 1]);
        pzp[q] = pk2(X[3 * i0 + 2], X[3 * i1 + 2]);
        dist[2 * q] = 1e38f;
        dist[2 * q + 1] = 1e38f;
    }

    __shared__ unsigned s_wv[32];
    __shared__ int      s_wi[32];
    __shared__ int      s_widx;

    float lx = X[0], ly = X[1], lz = X[2];   // first center = point 0
    if (t == 0) { O[0] = lx; O[1] = ly; O[2] = lz; }

    for (int k = 1; k < NPOINT; k++) {
        // Broadcast negated center, packed into both halves.
        const unsigned nbx = __float_as_uint(lx) ^ 0x80000000u;
        const unsigned nby = __float_as_uint(ly) ^ 0x80000000u;
        const unsigned nbz = __float_as_uint(lz) ^ 0x80000000u;
        const u64 nlx2 = pk2(__uint_as_float(nbx), __uint_as_float(nbx));
        const u64 nly2 = pk2(__uint_as_float(nby), __uint_as_float(nby));
        const u64 nlz2 = pk2(__uint_as_float(nbz), __uint_as_float(nbz));

#pragma unroll
        for (int q = 0; q < 4; q++) {
            const u64 dx = addx2(pxp[q], nlx2);
            const u64 dy = addx2(pyp[q], nly2);
            const u64 dz = addx2(pzp[q], nlz2);
            // ((dx^2 + dy^2) + dz^2) — same association as the reference.
            const u64 s = addx2(addx2(mulx2(dx, dx), mulx2(dy, dy)),
                                mulx2(dz, dz));
            const float2 d2 = upk2(s);
            dist[2 * q]     = fminf(dist[2 * q],     d2.x);
            dist[2 * q + 1] = fminf(dist[2 * q + 1], d2.y);
        }

        // Thread-local max (FMNMX tree; all values >= 0, no NaN).
        const float m01 = fmaxf(dist[0], dist[1]);
        const float m23 = fmaxf(dist[2], dist[3]);
        const float m45 = fmaxf(dist[4], dist[5]);
        const float m67 = fmaxf(dist[6], dist[7]);
        const float best = fmaxf(fmaxf(m01, m23), fmaxf(m45, m67));

        // Warp argmax: float bits of non-negative floats are order-preserving
        // as u32. Index recovery deferred: only warps containing the max pay
        // for the scan. Ties -> min index (first occurrence, jnp.argmax).
        const unsigned vb = __float_as_uint(best);
        const unsigned wmax = redux_max_u32(vb);
        int cand = 0x7fffffff;
        if (vb == wmax) {
#pragma unroll
            for (int j = 7; j >= 0; j--)
                if (__float_as_uint(dist[j]) == wmax) cand = j * 1024 + t;
        }
        const int wimin = redux_min_s32(cand);

        if ((t & 31) == 0) { s_wv[t >> 5] = wmax; s_wi[t >> 5] = wimin; }
        __syncthreads();

        if (t < 32) {
            const unsigned v2 = s_wv[t];
            const int      i2 = s_wi[t];
            const unsigned m2 = redux_max_u32(v2);
            const int c2 = (v2 == m2) ? i2 : 0x7fffffff;
            const int w2 = redux_min_s32(c2);
            if (t == 0) s_widx = w2;
        }
        __syncthreads();

        const int wi = s_widx;
        lx = __ldg(X + 3 * wi + 0);   // uniform broadcast load, L1-resident
        ly = __ldg(X + 3 * wi + 1);
        lz = __ldg(X + 3 * wi + 2);
        if (t == 0) { O[3 * k] = lx; O[3 * k + 1] = ly; O[3 * k + 2] = lz; }
    }
}

// ---------------------------------------------------------------------------
// Kernel 2: fused ball query + grouping — round-10 version VERBATIM (best
// measured: 84us). One warp per center. The in-radius scan batches 8 ballots
// (256 points) per early-exit check: loads/math are independent (deep MLP);
// the serialized cnt/ballot chain is 8x shorter than the per-32 version.
// ---------------------------------------------------------------------------
__global__ __launch_bounds__(256)
void ballgroup_kernel(const float* __restrict__ xyz,
                      const float* __restrict__ points,
                      const float* __restrict__ new_xyz,
                      float* __restrict__ new_points) {
    const int gwarp = (blockIdx.x * blockDim.x + threadIdx.x) >> 5;
    const int lane  = threadIdx.x & 31;
    const int wslot = threadIdx.x >> 5;
    if (gwarp >= BATCH * NPOINT) return;

    const int b = gwarp / NPOINT;
    const int p = gwarp % NPOINT;

    const float* X   = xyz    + (size_t)b * NPTS * 3;
    const float* P   = points + (size_t)b * NPTS * CFEAT;
    const float* ctr = new_xyz + (size_t)(b * NPOINT + p) * 3;
    const float cx = ctr[0], cy = ctr[1], cz = ctr[2];

    __shared__ int sidx[8][NSAMPLE];

    const unsigned lmask = (1u << lane) - 1u;
    int cnt = 0;
    for (int sb = 0; sb < NPTS && cnt < NSAMPLE; sb += 256) {
        unsigned m[8];
#pragma unroll
        for (int c = 0; c < 8; c++) {
            const int i = sb + c * 32 + lane;
            const float dx = X[3 * i + 0] - cx;
            const float dy = X[3 * i + 1] - cy;
            const float dz = X[3 * i + 2] - cz;
            const float d2 = __fadd_rn(__fadd_rn(__fmul_rn(dx, dx),
                                                 __fmul_rn(dy, dy)),
                                       __fmul_rn(dz, dz));
            m[c] = __ballot_sync(0xffffffff, d2 < R2);
        }
#pragma unroll
        for (int c = 0; c < 8; c++) {
            const int i = sb + c * 32 + lane;
            const bool in = (m[c] >> lane) & 1u;
            const int pos = cnt + __popc(m[c] & lmask);
            if (in && pos < NSAMPLE) sidx[wslot][pos] = i;
            cnt += __popc(m[c]);
        }
    }
    __syncwarp();

    // Pad: every center contains itself (d2 == 0 < R2), so cnt >= 1.
    const int nvalid = cnt < NSAMPLE ? cnt : NSAMPLE;
    const int first  = sidx[wslot][0];
    const int myidx  = (lane < nvalid) ? sidx[wslot][lane] : first;
    sidx[wslot][lane] = myidx;
    __syncwarp();

    float* OUT = new_points + (size_t)(b * NPOINT + p) * NSAMPLE * OUTC;
    const float cc = (lane == 0) ? cx : ((lane == 1) ? cy : cz);

#pragma unroll
    for (int s0 = 0; s0 < NSAMPLE; s0 += 4) {
        int id[4];
#pragma unroll
        for (int u = 0; u < 4; u++) id[u] = sidx[wslot][s0 + u];
#pragma unroll
        for (int u = 0; u < 4; u++) {
            const int idx = id[u];
            float v;
            if (lane < 3) {
                v = X[3 * idx + lane] - cc;                   // centered xyz
            } else {
                v = P[(size_t)idx * CFEAT + (lane - 3)];      // feature 0..28
            }
            OUT[(s0 + u) * OUTC + lane] = v;
            if (lane < 3) {                                    // feature 29..31
                OUT[(s0 + u) * OUTC + 32 + lane] =
                    P[(size_t)idx * CFEAT + 29 + lane];
            }
        }
    }
}

// ---------------------------------------------------------------------------
// Launch: d_in[0] = xyz (8*8192*3 f32), d_in[1] = points (8*8192*32 f32).
// d_out = [ new_xyz : 8*1024*3 ][ new_points : 8*1024*32*35 ] f32.
// ---------------------------------------------------------------------------
extern "C" void kernel_launch(void* const* d_in, const int* in_sizes, int n_in,
                              void* d_out, int out_size) {
    const float* xyz    = (const float*)d_in[0];
    const float* points = (const float*)d_in[1];
    float* new_xyz    = (float*)d_out;
    float* new_points = new_xyz + (size_t)BATCH * NPOINT * 3;

    fps_kernel<<<BATCH, 1024>>>(xyz, new_xyz);

    const int nwarps  = BATCH * NPOINT;            // 8192 centers
    const int threads = 256;                       // 8 warps/block
    const int blocks  = (nwarps * 32) / threads;   // 1024 blocks
    ballgroup_kernel<<<blocks, threads>>>(xyz, points, new_xyz, new_points);
}